// round 15
// baseline (speedup 1.0000x reference)
#include <cuda_runtime.h>
#include <cuda_fp16.h>
#include <cstdint>

// Problem constants: B=8192, F=256, T=32, D=6 -> N=63, L=64, P=8
constexpr int B_     = 8192;
constexpr int F_     = 256;
constexpr int T_     = 32;
constexpr int NNODES = 63;
constexpr int LEAVES = 64;
constexpr int P_     = 8;

constexpr int BM = 128;
constexpr int BN = 64;
constexpr int NTHREADS = 256;        // 8 warps: 4(m) x 2(n), warp tile 32x32
constexpr int TREES_PER_BLK = 4;
constexpr int NGRP = T_ / TREES_PER_BLK;   // 8
constexpr int NTILES = B_ / BM;            // 64

// K-split staging: half of K (=128) resident at a time.
constexpr int KH  = 128;             // K per stage
constexpr int LDK = KH + 8;          // 136 halfs/row -> 272B stride, 16B aligned
constexpr int SMEM_A_BYTES = BM * LDK * 2;     // 34816
constexpr int SMEM_BS_REGION = 32768;          // max(Bs-half 17408, s_tile 32768)
constexpr int SMEM_DYN = SMEM_A_BYTES + SMEM_BS_REGION;   // 67584 -> 3 CTAs/SM

// Scratch: per tree-group partials + fp16-converted inputs.
__device__ __align__(16) float  g_partial[(size_t)NGRP * B_ * P_];
__device__ int g_cnt[NTILES];   // zero-initialized; reset by last CTA (graph replays)
__device__ __align__(16) __half g_xh[(size_t)B_ * F_];
__device__ __align__(16) __half g_wh[(size_t)T_ * NNODES * F_];

__device__ __forceinline__ uint32_t smem_u32(const void* p) {
    uint32_t a;
    asm("{ .reg .u64 t; cvta.to.shared.u64 t, %1; cvt.u32.u64 %0, t; }"
        : "=r"(a) : "l"(p));
    return a;
}
__device__ __forceinline__ void ldmatrix_x4(uint32_t& r0, uint32_t& r1,
                                            uint32_t& r2, uint32_t& r3, uint32_t addr) {
    asm volatile("ldmatrix.sync.aligned.m8n8.x4.shared.b16 {%0,%1,%2,%3}, [%4];"
                 : "=r"(r0), "=r"(r1), "=r"(r2), "=r"(r3) : "r"(addr));
}
__device__ __forceinline__ void mma16816(float* c, uint32_t a0, uint32_t a1,
                                         uint32_t a2, uint32_t a3,
                                         uint32_t b0, uint32_t b1) {
    asm volatile(
        "mma.sync.aligned.m16n8k16.row.col.f32.f16.f16.f32 "
        "{%0,%1,%2,%3}, {%4,%5,%6,%7}, {%8,%9}, {%0,%1,%2,%3};"
        : "+f"(c[0]), "+f"(c[1]), "+f"(c[2]), "+f"(c[3])
        : "r"(a0), "r"(a1), "r"(a2), "r"(a3), "r"(b0), "r"(b1));
}
__device__ __forceinline__ float sigmoidf(float v) {
    return __fdividef(1.0f, 1.0f + __expf(-v));
}
__device__ __forceinline__ void prefetch_l2(const void* p) {
    asm volatile("prefetch.global.L2 [%0];" :: "l"(p));
}
// Bank bijection: 4 row bits -> bank bits {0,1,3,4} (disjoint from tig bits {1,2}).
__device__ __forceinline__ uint32_t vswz(uint32_t rl) {
    return ((rl & 3u) << 3) | ((rl >> 2) & 1u) | (((rl >> 3) & 1u) << 1);
}

// ---------------- prep: fp32 -> fp16 conversion of x and W ----------------
__global__ void softgbm_prep(const float* __restrict__ x, const float* __restrict__ W) {
    int i = blockIdx.x * blockDim.x + threadIdx.x;
    constexpr int NX4 = B_ * F_ / 4;
    constexpr int NW4 = T_ * NNODES * F_ / 4;
    if (i < NX4) {
        float4 v = reinterpret_cast<const float4*>(x)[i];
        __half2* o = reinterpret_cast<__half2*>(g_xh);
        o[2 * i]     = __floats2half2_rn(v.x, v.y);
        o[2 * i + 1] = __floats2half2_rn(v.z, v.w);
    } else if (i < NX4 + NW4) {
        int j = i - NX4;
        float4 v = reinterpret_cast<const float4*>(W)[j];
        __half2* o = reinterpret_cast<__half2*>(g_wh);
        o[2 * j]     = __floats2half2_rn(v.x, v.y);
        o[2 * j + 1] = __floats2half2_rn(v.z, v.w);
    }
}

__global__ __launch_bounds__(NTHREADS, 3)
void softgbm_main_kernel(const float* __restrict__ bias,
                         const float* __restrict__ phi,
                         float* __restrict__ out) {
    extern __shared__ __align__(16) char dsm[];
    __shared__ float phi_s[LEAVES * P_];
    __shared__ float b_s[BN];
    __shared__ int s_last;

    __half* As = reinterpret_cast<__half*>(dsm);                 // [128][LDK] (one k-half)
    __half* Bs = reinterpret_cast<__half*>(dsm + SMEM_A_BYTES);  // [64][LDK]  (one k-half)
    char* s_base = dsm + SMEM_A_BYTES;   // s_tile fp32 [128][64] v-swizzled, aliases Bs
    // LP buffers live in the As region (dead between GEMM h1 and next tree's fill)
    const int tid  = threadIdx.x;
    const int wid  = tid >> 5;
    const int lane = tid & 31;
    const int tgrp = blockIdx.y;
    const int bx   = blockIdx.x;
    const int row0 = bx * BM;

    const int warp_m = wid >> 1;
    const int warp_n = wid & 1;
    const int gi  = lane >> 2;     // 0..7
    const int tig = lane & 3;      // 0..3

    char* lp_base = dsm + wid * 2048;   // 16 rows x 128B per warp, inside As region

    const uint32_t as_u32 = smem_u32(As);
    const uint32_t bs_u32 = smem_u32(Bs);
    const uint32_t a_lm = as_u32 +
        ((uint32_t)(warp_m * 32 + (lane & 15)) * LDK + (lane >> 4) * 8) * 2;
    const uint32_t b_lm = bs_u32 +
        ((uint32_t)(warp_n * 32 + ((lane >> 4) & 1) * 8 + (lane & 7)) * LDK +
         ((lane >> 3) & 1) * 8) * 2;

    const int r_leaf = tid >> 1;
    const int q      = tid & 1;
    const uint32_t v_leaf = vswz((uint32_t)r_leaf & 15);
    const int rl7 = r_leaf & 7;

    float accP[4] = {0.f, 0.f, 0.f, 0.f};

    const __half* xh = g_xh + (size_t)row0 * F_;

    for (int it_t = 0; it_t < TREES_PER_BLK; it_t++) {
        const int t = tgrp * TREES_PER_BLK + it_t;
        const __half* wh = g_wh + (size_t)t * NNODES * F_;

        // load phi/bias once per tree
        phi_s[tid]       = phi[(size_t)t * LEAVES * P_ + tid];
        phi_s[tid + 256] = phi[(size_t)t * LEAVES * P_ + tid + 256];
        if (tid < BN)
            b_s[tid] = (tid < NNODES) ? bias[(size_t)t * NNODES + tid] : 0.0f;

        float acc[2][4][4];
#pragma unroll
        for (int mi = 0; mi < 2; mi++)
#pragma unroll
            for (int ni = 0; ni < 4; ni++)
#pragma unroll
                for (int j = 0; j < 4; j++) acc[mi][ni][j] = 0.0f;

#pragma unroll
        for (int kh = 0; kh < 2; kh++) {
            const int k0 = kh * KH;

            // ---- fill As half: 2048 16B chunks / 256 thr = 8 each ----
#pragma unroll
            for (int it = 0; it < 8; it++) {
                int f = it * NTHREADS + tid;
                int r = f >> 4;            // 0..127
                int c = f & 15;            // 8-half chunk within k-half
                uint4 v = *reinterpret_cast<const uint4*>(
                    xh + (size_t)r * F_ + k0 + c * 8);
                *reinterpret_cast<uint4*>(As + (size_t)r * LDK + c * 8) = v;
            }
            // ---- fill Bs half: 1024 chunks / 256 thr = 4 each ----
#pragma unroll
            for (int it = 0; it < 4; it++) {
                int f = it * NTHREADS + tid;
                int n = f >> 4;            // 0..63
                int c = f & 15;
                uint4 v = make_uint4(0u, 0u, 0u, 0u);
                if (n < NNODES)
                    v = *reinterpret_cast<const uint4*>(
                        wh + (size_t)n * F_ + k0 + c * 8);
                *reinterpret_cast<uint4*>(Bs + (size_t)n * LDK + c * 8) = v;
            }
            __syncthreads();

            // prefetch next tree's W while first half computes
            if (kh == 0 && it_t + 1 < TREES_PER_BLK) {
                const char* wn = reinterpret_cast<const char*>(
                    wh + (size_t)NNODES * F_);
                if (tid < NNODES * F_ * 2 / 128)
                    prefetch_l2(wn + (size_t)tid * 128);
            }

            // ---- GEMM on this k-half: 8 k-steps ----
#pragma unroll
            for (int ks = 0; ks < 8; ks++) {
                const uint32_t kb = (uint32_t)ks * 32;
                uint32_t af[2][4], bf[4][2];
                ldmatrix_x4(af[0][0], af[0][1], af[0][2], af[0][3], a_lm + kb);
                ldmatrix_x4(af[1][0], af[1][1], af[1][2], af[1][3],
                            a_lm + kb + 16 * LDK * 2);
                ldmatrix_x4(bf[0][0], bf[0][1], bf[1][0], bf[1][1], b_lm + kb);
                ldmatrix_x4(bf[2][0], bf[2][1], bf[3][0], bf[3][1],
                            b_lm + kb + 16 * LDK * 2);
#pragma unroll
                for (int mi = 0; mi < 2; mi++)
#pragma unroll
                    for (int ni = 0; ni < 4; ni++)
                        mma16816(acc[mi][ni], af[mi][0], af[mi][1], af[mi][2], af[mi][3],
                                 bf[ni][0], bf[ni][1]);
            }
            __syncthreads();   // As/Bs reads done; next half (or s_tile) may overwrite
        }

        // ---- bias + sigmoid -> v-swizzled fp32 s_tile (conflict-free STS.32) ----
        {
            const uint32_t v_lo = vswz((uint32_t)gi);
            const uint32_t v_hi = v_lo | 2u;
#pragma unroll
            for (int mi = 0; mi < 2; mi++) {
                int r = warp_m * 32 + mi * 16 + gi;
                char* row_lo = s_base + (size_t)r * 256;
                char* row_hi = s_base + (size_t)(r + 8) * 256;
#pragma unroll
                for (int ni = 0; ni < 4; ni++) {
                    uint32_t c0 = (uint32_t)(warp_n * 32 + ni * 8 + tig * 2);
                    *reinterpret_cast<float*>(row_lo + ((c0 ^ v_lo) << 2)) =
                        sigmoidf(acc[mi][ni][0] + b_s[c0]);
                    *reinterpret_cast<float*>(row_lo + (((c0 + 1) ^ v_lo) << 2)) =
                        sigmoidf(acc[mi][ni][1] + b_s[c0 + 1]);
                    *reinterpret_cast<float*>(row_hi + ((c0 ^ v_hi) << 2)) =
                        sigmoidf(acc[mi][ni][2] + b_s[c0]);
                    *reinterpret_cast<float*>(row_hi + (((c0 + 1) ^ v_hi) << 2)) =
                        sigmoidf(acc[mi][ni][3] + b_s[c0 + 1]);
                }
            }
        }
        __syncthreads();

        // ---- build phi B-fragments (B[n=p][k=l] = phi[l][p]) from phi_s ----
        uint32_t bphi[4][2];
#pragma unroll
        for (int ks = 0; ks < 4; ks++) {
            int k0 = 16 * ks + 2 * tig;
            __half2 h0 = __floats2half2_rn(phi_s[k0 * P_ + gi],
                                           phi_s[(k0 + 1) * P_ + gi]);
            __half2 h1 = __floats2half2_rn(phi_s[(k0 + 8) * P_ + gi],
                                           phi_s[(k0 + 9) * P_ + gi]);
            bphi[ks][0] = *reinterpret_cast<uint32_t*>(&h0);
            bphi[ks][1] = *reinterpret_cast<uint32_t*>(&h1);
        }

        // ---- leaf probabilities (subtree q), LP streamed to As-region buffer ----
        {
            const char* srow = s_base + (size_t)r_leaf * 256;
            auto lds = [&](int n) -> float {
                return *reinterpret_cast<const float*>(
                    srow + ((((uint32_t)n) ^ v_leaf) << 2));
            };
            char* lw = lp_base + (size_t)(r_leaf & 15) * 128;
            const uint32_t swz = (uint32_t)rl7 << 4;

            float s0   = lds(0);
            float root = q ? s0 : 1.0f - s0;
            float sv   = lds(1 + q);
            float p2[2];
            p2[1] = root * sv; p2[0] = root - p2[1];
            float p4[4];
#pragma unroll
            for (int i = 0; i < 2; i++) {
                float s2 = lds(3 + 2 * q + i);
                p4[2 * i + 1] = p2[i] * s2; p4[2 * i] = p2[i] - p4[2 * i + 1];
            }
            float p8[8];
#pragma unroll
            for (int i = 0; i < 4; i++) {
                float s3 = lds(7 + 4 * q + i);
                p8[2 * i + 1] = p4[i] * s3; p8[2 * i] = p4[i] - p8[2 * i + 1];
            }
            float p16[16];
#pragma unroll
            for (int i = 0; i < 8; i++) {
                float s4 = lds(15 + 8 * q + i);
                p16[2 * i + 1] = p8[i] * s4; p16[2 * i] = p8[i] - p16[2 * i + 1];
            }
#pragma unroll
            for (int j = 0; j < 16; j++) {
                float s5  = lds(31 + 16 * q + j);
                float pr1 = p16[j] * s5;
                float pr0 = p16[j] - pr1;
                __half2 h = __floats2half2_rn(pr0, pr1);
                uint32_t kb = (uint32_t)(q * 64 + 4 * j);
                *reinterpret_cast<__half2*>(lw + (kb ^ swz)) = h;
            }
        }
        __syncwarp();   // warp-local LP stores visible before contraction reads

        // ---- contraction MMA: LP[16x64] x phiT -> accP (accumulates over trees) ----
        {
            const uint32_t swzA = (uint32_t)gi << 4;
#pragma unroll
            for (int ks = 0; ks < 4; ks++) {
                uint32_t kb = (uint32_t)(32 * ks + 4 * tig);
                uint32_t a0 = *reinterpret_cast<const uint32_t*>(
                    lp_base + (size_t)gi * 128 + (kb ^ swzA));
                uint32_t a1 = *reinterpret_cast<const uint32_t*>(
                    lp_base + (size_t)(gi + 8) * 128 + (kb ^ swzA));
                uint32_t a2 = *reinterpret_cast<const uint32_t*>(
                    lp_base + (size_t)gi * 128 + ((kb + 16) ^ swzA));
                uint32_t a3 = *reinterpret_cast<const uint32_t*>(
                    lp_base + (size_t)(gi + 8) * 128 + ((kb + 16) ^ swzA));
                mma16816(accP, a0, a1, a2, a3, bphi[ks][0], bphi[ks][1]);
            }
        }
        __syncthreads();   // LP (As region) + s_tile reads done; next tree may refill
    }

    // ---- write this group's partial in MMA layout ----
    {
        int rg = row0 + 16 * wid + gi;
        float* o0 = g_partial + (size_t)tgrp * B_ * P_ + (size_t)rg * P_ + 2 * tig;
        float* o1 = o0 + 8 * P_;
        *reinterpret_cast<float2*>(o0) = make_float2(accP[0], accP[1]);
        *reinterpret_cast<float2*>(o1) = make_float2(accP[2], accP[3]);
    }

    // ---- fused tail reduction: last CTA of this batch-tile sums all 8 groups ----
    __threadfence();
    __syncthreads();
    if (tid == 0) {
        int old = atomicAdd(&g_cnt[bx], 1);
        s_last = (old == NGRP - 1) ? 1 : 0;
        if (s_last) g_cnt[bx] = 0;     // reset for next graph replay
    }
    __syncthreads();
    if (s_last) {
        __threadfence();               // acquire side of the counter handshake
        const size_t base = (size_t)row0 * P_ / 4;   // float4 units
        float4 s = make_float4(0.f, 0.f, 0.f, 0.f);
#pragma unroll
        for (int g = 0; g < NGRP; g++) {
            const float4* gp = reinterpret_cast<const float4*>(
                g_partial + (size_t)g * B_ * P_);
            float4 v = gp[base + tid];
            s.x += v.x; s.y += v.y; s.z += v.z; s.w += v.w;
        }
        s.x *= 0.1f; s.y *= 0.1f; s.z *= 0.1f; s.w *= 0.1f;
        reinterpret_cast<float4*>(out)[base + tid] = s;
    }
}

extern "C" void kernel_launch(void* const* d_in, const int* in_sizes, int n_in,
                              void* d_out, int out_size) {
    (void)in_sizes; (void)n_in; (void)out_size;
    const float* x    = (const float*)d_in[0];
    const float* W    = (const float*)d_in[1];
    const float* bias = (const float*)d_in[2];
    const float* phi  = (const float*)d_in[3];
    float* out = (float*)d_out;

    cudaFuncSetAttribute(softgbm_main_kernel,
                         cudaFuncAttributeMaxDynamicSharedMemorySize, SMEM_DYN);

    constexpr int NCVT = (B_ * F_ + T_ * NNODES * F_) / 4;
    softgbm_prep<<<(NCVT + 255) / 256, 256>>>(x, W);

    dim3 grid(NTILES, NGRP);   // (64, 8) = 512 CTAs
    softgbm_main_kernel<<<grid, NTHREADS, SMEM_DYN>>>(bias, phi, out);
}

// round 16
// speedup vs baseline: 1.2856x; 1.2856x over previous
#include <cuda_runtime.h>
#include <cuda_fp16.h>
#include <cstdint>

// Problem constants: B=8192, F=256, T=32, D=6 -> N=63, L=64, P=8
constexpr int B_     = 8192;
constexpr int F_     = 256;
constexpr int T_     = 32;
constexpr int NNODES = 63;
constexpr int LEAVES = 64;
constexpr int P_     = 8;

constexpr int BM = 128;
constexpr int BN = 64;
constexpr int NTHREADS = 256;        // 8 warps: 4(m) x 2(n), warp tile 32x32
constexpr int TREES_PER_BLK = 4;
constexpr int NGRP = T_ / TREES_PER_BLK;   // 8
constexpr int NTILES = B_ / BM;            // 64

constexpr int LDA = F_ + 8;          // 264 halfs/row
constexpr int LDB = F_ + 8;
constexpr int SMEM_A_BYTES = BM * LDA * 2;                 // 67584
constexpr int SMEM_B_BYTES = BN * LDB * 2;                 // 33792 (>= s_tile 32768)
constexpr int SMEM_DYN     = SMEM_A_BYTES + SMEM_B_BYTES;  // 101376 -> 2 CTAs/SM

// Scratch: per tree-group partials + fp16-converted inputs.
__device__ __align__(16) float  g_partial[(size_t)NGRP * B_ * P_];
__device__ int g_cnt[NTILES];   // zero-initialized; reset by last CTA (graph replays)
__device__ __align__(16) __half g_xh[(size_t)B_ * F_];
__device__ __align__(16) __half g_wh[(size_t)T_ * NNODES * F_];

__device__ __forceinline__ uint32_t smem_u32(const void* p) {
    uint32_t a;
    asm("{ .reg .u64 t; cvta.to.shared.u64 t, %1; cvt.u32.u64 %0, t; }"
        : "=r"(a) : "l"(p));
    return a;
}
__device__ __forceinline__ void ldmatrix_x4(uint32_t& r0, uint32_t& r1,
                                            uint32_t& r2, uint32_t& r3, uint32_t addr) {
    asm volatile("ldmatrix.sync.aligned.m8n8.x4.shared.b16 {%0,%1,%2,%3}, [%4];"
                 : "=r"(r0), "=r"(r1), "=r"(r2), "=r"(r3) : "r"(addr));
}
__device__ __forceinline__ void mma16816(float* c, uint32_t a0, uint32_t a1,
                                         uint32_t a2, uint32_t a3,
                                         uint32_t b0, uint32_t b1) {
    asm volatile(
        "mma.sync.aligned.m16n8k16.row.col.f32.f16.f16.f32 "
        "{%0,%1,%2,%3}, {%4,%5,%6,%7}, {%8,%9}, {%0,%1,%2,%3};"
        : "+f"(c[0]), "+f"(c[1]), "+f"(c[2]), "+f"(c[3])
        : "r"(a0), "r"(a1), "r"(a2), "r"(a3), "r"(b0), "r"(b1));
}
__device__ __forceinline__ float sigmoidf(float v) {
    return __fdividef(1.0f, 1.0f + __expf(-v));
}
__device__ __forceinline__ void prefetch_l2(const void* p) {
    asm volatile("prefetch.global.L2 [%0];" :: "l"(p));
}
__device__ __forceinline__ void bar_pair(int barid) {
    asm volatile("bar.sync %0, 64;" :: "r"(barid) : "memory");
}
// Bank bijection: 4 row bits -> bank bits {0,1,3,4} (disjoint from tig bits {1,2}).
__device__ __forceinline__ uint32_t vswz(uint32_t rl) {
    return ((rl & 3u) << 3) | ((rl >> 2) & 1u) | (((rl >> 3) & 1u) << 1);
}

// ---------------- prep: fp32 -> fp16 conversion of x and W ----------------
__global__ void softgbm_prep(const float* __restrict__ x, const float* __restrict__ W) {
    int i = blockIdx.x * blockDim.x + threadIdx.x;
    constexpr int NX4 = B_ * F_ / 4;
    constexpr int NW4 = T_ * NNODES * F_ / 4;
    if (i < NX4) {
        float4 v = reinterpret_cast<const float4*>(x)[i];
        __half2* o = reinterpret_cast<__half2*>(g_xh);
        o[2 * i]     = __floats2half2_rn(v.x, v.y);
        o[2 * i + 1] = __floats2half2_rn(v.z, v.w);
    } else if (i < NX4 + NW4) {
        int j = i - NX4;
        float4 v = reinterpret_cast<const float4*>(W)[j];
        __half2* o = reinterpret_cast<__half2*>(g_wh);
        o[2 * j]     = __floats2half2_rn(v.x, v.y);
        o[2 * j + 1] = __floats2half2_rn(v.z, v.w);
    }
}

__global__ __launch_bounds__(NTHREADS, 2)
void softgbm_main_kernel(const float* __restrict__ bias,
                         const float* __restrict__ phi,
                         float* __restrict__ out) {
    extern __shared__ __align__(16) char dsm[];
    __shared__ float phi_s[LEAVES * P_];
    __shared__ float b_s[BN];
    __shared__ int s_last;

    __half* As = reinterpret_cast<__half*>(dsm);                 // [128][LDA]
    __half* Bs = reinterpret_cast<__half*>(dsm + SMEM_A_BYTES);  // [64][LDB]
    // s_tile: fp32 [128 rows][64 cols], row stride 256B, v-swizzled columns.
    char* s_base = dsm + SMEM_A_BYTES;                           // aliases Bs

    const int tid  = threadIdx.x;
    const int wid  = tid >> 5;
    const int lane = tid & 31;
    const int tgrp = blockIdx.y;
    const int bx   = blockIdx.x;
    const int row0 = bx * BM;

    const int warp_m = wid >> 1;
    const int warp_n = wid & 1;
    const int gi  = lane >> 2;     // 0..7
    const int tig = lane & 3;      // 0..3
    const int pair_bar = 1 + warp_m;   // named barrier id for warp pair {2m, 2m+1}

    // ---- fill As once from pre-converted fp16 x ----
    {
        const __half* xh = g_xh + (size_t)row0 * F_;
#pragma unroll
        for (int it = 0; it < 16; it++) {
            int f = it * NTHREADS + tid;   // 0..4095 16B chunks
            int r = f >> 5;
            int c = f & 31;
            uint4 v = *reinterpret_cast<const uint4*>(xh + (size_t)r * F_ + c * 8);
            *reinterpret_cast<uint4*>(As + (size_t)r * LDA + c * 8) = v;
        }
    }

    const uint32_t as_u32 = smem_u32(As);
    const uint32_t bs_u32 = smem_u32(Bs);
    const uint32_t a_lm = as_u32 +
        ((uint32_t)(warp_m * 32 + (lane & 15)) * LDA + (lane >> 4) * 8) * 2;
    const uint32_t b_lm = bs_u32 +
        ((uint32_t)(warp_n * 32 + ((lane >> 4) & 1) * 8 + (lane & 7)) * LDB +
         ((lane >> 3) & 1) * 8) * 2;

    // leafprob mapping: thread handles row r_leaf (warp wid owns rows 16w..16w+15)
    const int r_leaf = tid >> 1;
    const int q      = tid & 1;
    const uint32_t v_leaf = vswz((uint32_t)r_leaf & 15);
    const int rl7 = r_leaf & 7;

    // per-warp LP buffer: 16 rows x 64 halves (128B/row, 16B-granule XOR swizzle),
    // placed at this warp's OWN s_tile rows -> no extra smem.
    char* lp_base = s_base + wid * 4096;

    float accP[4] = {0.f, 0.f, 0.f, 0.f};

    for (int it_t = 0; it_t < TREES_PER_BLK; it_t++) {
        const int t = tgrp * TREES_PER_BLK + it_t;

        // ---- fill Bs from pre-converted fp16 W ----
        const __half* wh = g_wh + (size_t)t * NNODES * F_;
#pragma unroll
        for (int it = 0; it < 8; it++) {
            int f = it * NTHREADS + tid;   // 0..2047 16B chunks
            int n = f >> 5;
            int c = f & 31;
            uint4 v = make_uint4(0u, 0u, 0u, 0u);
            if (n < NNODES)
                v = *reinterpret_cast<const uint4*>(wh + (size_t)n * F_ + c * 8);
            *reinterpret_cast<uint4*>(Bs + (size_t)n * LDB + c * 8) = v;
        }
        phi_s[tid]       = phi[(size_t)t * LEAVES * P_ + tid];
        phi_s[tid + 256] = phi[(size_t)t * LEAVES * P_ + tid + 256];
        if (tid < BN)
            b_s[tid] = (tid < NNODES) ? bias[(size_t)t * NNODES + tid] : 0.0f;
        __syncthreads();

        // L2-prefetch next tree's W (fp16: 32KB = 252 lines)
        if (it_t + 1 < TREES_PER_BLK) {
            const char* wn = reinterpret_cast<const char*>(
                g_wh + (size_t)(t + 1) * NNODES * F_);
            if (tid < NNODES * F_ * 2 / 128)
                prefetch_l2(wn + (size_t)tid * 128);
        }

        // ---- GEMM: 16 k-steps, ldmatrix fragments ----
        float acc[2][4][4];
#pragma unroll
        for (int mi = 0; mi < 2; mi++)
#pragma unroll
            for (int ni = 0; ni < 4; ni++)
#pragma unroll
                for (int j = 0; j < 4; j++) acc[mi][ni][j] = 0.0f;

#pragma unroll
        for (int ks = 0; ks < 16; ks++) {
            const uint32_t kb = (uint32_t)ks * 32;
            uint32_t af[2][4], bf[4][2];
            ldmatrix_x4(af[0][0], af[0][1], af[0][2], af[0][3], a_lm + kb);
            ldmatrix_x4(af[1][0], af[1][1], af[1][2], af[1][3],
                        a_lm + kb + 16 * LDA * 2);
            ldmatrix_x4(bf[0][0], bf[0][1], bf[1][0], bf[1][1], b_lm + kb);
            ldmatrix_x4(bf[2][0], bf[2][1], bf[3][0], bf[3][1],
                        b_lm + kb + 16 * LDB * 2);
#pragma unroll
            for (int mi = 0; mi < 2; mi++)
#pragma unroll
                for (int ni = 0; ni < 4; ni++)
                    mma16816(acc[mi][ni], af[mi][0], af[mi][1], af[mi][2], af[mi][3],
                             bf[ni][0], bf[ni][1]);
        }
        __syncthreads();   // Bs reads done; s_tile may overwrite

        // ---- bias + sigmoid -> v-swizzled fp32 s_tile (conflict-free STS.32) ----
        {
            const uint32_t v_lo = vswz((uint32_t)gi);
            const uint32_t v_hi = v_lo | 2u;
#pragma unroll
            for (int mi = 0; mi < 2; mi++) {
                int r = warp_m * 32 + mi * 16 + gi;
                char* row_lo = s_base + (size_t)r * 256;
                char* row_hi = s_base + (size_t)(r + 8) * 256;
#pragma unroll
                for (int ni = 0; ni < 4; ni++) {
                    uint32_t c0 = (uint32_t)(warp_n * 32 + ni * 8 + tig * 2);
                    *reinterpret_cast<float*>(row_lo + ((c0 ^ v_lo) << 2)) =
                        sigmoidf(acc[mi][ni][0] + b_s[c0]);
                    *reinterpret_cast<float*>(row_lo + (((c0 + 1) ^ v_lo) << 2)) =
                        sigmoidf(acc[mi][ni][1] + b_s[c0 + 1]);
                    *reinterpret_cast<float*>(row_hi + ((c0 ^ v_hi) << 2)) =
                        sigmoidf(acc[mi][ni][2] + b_s[c0]);
                    *reinterpret_cast<float*>(row_hi + (((c0 + 1) ^ v_hi) << 2)) =
                        sigmoidf(acc[mi][ni][3] + b_s[c0 + 1]);
                }
            }
        }
        // Pair-local exchange: warp pair {2m, 2m+1} wrote s_tile rows 32m..32m+31;
        // exactly those two warps read rows 16w..16w+15 in the leaf phase.
        bar_pair(pair_bar);

        // ---- build phi B-fragments (B[n=p][k=l] = phi[l][p]) from phi_s ----
        uint32_t bphi[4][2];
#pragma unroll
        for (int ks = 0; ks < 4; ks++) {
            int k0 = 16 * ks + 2 * tig;
            __half2 h0 = __floats2half2_rn(phi_s[k0 * P_ + gi],
                                           phi_s[(k0 + 1) * P_ + gi]);
            __half2 h1 = __floats2half2_rn(phi_s[(k0 + 8) * P_ + gi],
                                           phi_s[(k0 + 9) * P_ + gi]);
            bphi[ks][0] = *reinterpret_cast<uint32_t*>(&h0);
            bphi[ks][1] = *reinterpret_cast<uint32_t*>(&h1);
        }

        // ---- leaf probabilities (level-by-level, subtree q) -> fp16 LP ----
        __half2 lp[16];
        {
            const char* srow = s_base + (size_t)r_leaf * 256;
            auto lds = [&](int n) -> float {
                return *reinterpret_cast<const float*>(
                    srow + ((((uint32_t)n) ^ v_leaf) << 2));
            };
            float s0   = lds(0);
            float root = q ? s0 : 1.0f - s0;
            float sv   = lds(1 + q);
            float p2[2];
            p2[1] = root * sv; p2[0] = root - p2[1];
            float p4[4];
#pragma unroll
            for (int i = 0; i < 2; i++) {
                float s2 = lds(3 + 2 * q + i);
                p4[2 * i + 1] = p2[i] * s2; p4[2 * i] = p2[i] - p4[2 * i + 1];
            }
            float p8[8];
#pragma unroll
            for (int i = 0; i < 4; i++) {
                float s3 = lds(7 + 4 * q + i);
                p8[2 * i + 1] = p4[i] * s3; p8[2 * i] = p4[i] - p8[2 * i + 1];
            }
            float p16[16];
#pragma unroll
            for (int i = 0; i < 8; i++) {
                float s4 = lds(15 + 8 * q + i);
                p16[2 * i + 1] = p8[i] * s4; p16[2 * i] = p8[i] - p16[2 * i + 1];
            }
#pragma unroll
            for (int j = 0; j < 16; j++) {
                float s5  = lds(31 + 16 * q + j);
                float pr1 = p16[j] * s5;
                float pr0 = p16[j] - pr1;
                lp[j] = __floats2half2_rn(pr0, pr1);
            }
        }
        __syncwarp();   // all s reads of this warp's rows done before LP overwrites

        // store LP: local row = r_leaf & 15, khalf = q*32 + 2j (16B-granule XOR)
        {
            char* lw = lp_base + (size_t)(r_leaf & 15) * 128;
            const uint32_t swz = (uint32_t)rl7 << 4;
#pragma unroll
            for (int j = 0; j < 16; j++) {
                uint32_t kb = (uint32_t)(q * 64 + 4 * j);
                *reinterpret_cast<__half2*>(lw + (kb ^ swz)) = lp[j];
            }
        }
        __syncwarp();

        // ---- contraction MMA: LP[16x64] x phiT -> accP (accumulates over trees) ----
        {
            const uint32_t swzA = (uint32_t)gi << 4;
#pragma unroll
            for (int ks = 0; ks < 4; ks++) {
                uint32_t kb = (uint32_t)(32 * ks + 4 * tig);
                uint32_t a0 = *reinterpret_cast<const uint32_t*>(
                    lp_base + (size_t)gi * 128 + (kb ^ swzA));
                uint32_t a1 = *reinterpret_cast<const uint32_t*>(
                    lp_base + (size_t)(gi + 8) * 128 + (kb ^ swzA));
                uint32_t a2 = *reinterpret_cast<const uint32_t*>(
                    lp_base + (size_t)gi * 128 + ((kb + 16) ^ swzA));
                uint32_t a3 = *reinterpret_cast<const uint32_t*>(
                    lp_base + (size_t)(gi + 8) * 128 + ((kb + 16) ^ swzA));
                mma16816(accP, a0, a1, a2, a3, bphi[ks][0], bphi[ks][1]);
            }
        }
        __syncthreads();   // region reads done; next tree may refill Bs
    }

    // ---- write this group's partial in MMA layout ----
    {
        int rg = row0 + 16 * wid + gi;
        float* o0 = g_partial + (size_t)tgrp * B_ * P_ + (size_t)rg * P_ + 2 * tig;
        float* o1 = o0 + 8 * P_;
        *reinterpret_cast<float2*>(o0) = make_float2(accP[0], accP[1]);
        *reinterpret_cast<float2*>(o1) = make_float2(accP[2], accP[3]);
    }

    // ---- fused tail reduction: last CTA of this batch-tile sums all 8 groups ----
    __threadfence();
    __syncthreads();
    if (tid == 0) {
        int old = atomicAdd(&g_cnt[bx], 1);
        s_last = (old == NGRP - 1) ? 1 : 0;
        if (s_last) g_cnt[bx] = 0;     // reset for next graph replay
    }
    __syncthreads();
    if (s_last) {
        __threadfence();               // acquire side of the counter handshake
        const size_t base = (size_t)row0 * P_ / 4;   // float4 units
        float4 s = make_float4(0.f, 0.f, 0.f, 0.f);
#pragma unroll
        for (int g = 0; g < NGRP; g++) {
            const float4* gp = reinterpret_cast<const float4*>(
                g_partial + (size_t)g * B_ * P_);
            float4 v = gp[base + tid];
            s.x += v.x; s.y += v.y; s.z += v.z; s.w += v.w;
        }
        s.x *= 0.1f; s.y *= 0.1f; s.z *= 0.1f; s.w *= 0.1f;
        reinterpret_cast<float4*>(out)[base + tid] = s;
    }
}

extern "C" void kernel_launch(void* const* d_in, const int* in_sizes, int n_in,
                              void* d_out, int out_size) {
    (void)in_sizes; (void)n_in; (void)out_size;
    const float* x    = (const float*)d_in[0];
    const float* W    = (const float*)d_in[1];
    const float* bias = (const float*)d_in[2];
    const float* phi  = (const float*)d_in[3];
    float* out = (float*)d_out;

    cudaFuncSetAttribute(softgbm_main_kernel,
                         cudaFuncAttributeMaxDynamicSharedMemorySize, SMEM_DYN);

    constexpr int NCVT = (B_ * F_ + T_ * NNODES * F_) / 4;
    softgbm_prep<<<(NCVT + 255) / 256, 256>>>(x, W);

    dim3 grid(NTILES, NGRP);   // (64, 8) = 512 CTAs
    softgbm_main_kernel<<<grid, NTHREADS, SMEM_DYN>>>(bias, phi, out);
}